// round 2
// baseline (speedup 1.0000x reference)
#include <cuda_runtime.h>
#include <cstdint>

// ---------------------------------------------------------------------------
// AdditiveGaussianIMDPCertifier: iterated CSR row-sum
//   gamma_new[j] = clip(1 - sum_k b[j,k] * (1 - gamma[nbr[j,k]]), 0, 1)
// Inputs (metadata order):
//   d_in[0] gamma0       float32 [n]
//   d_in[1] bound_lower  float32 [ne]
//   d_in[2] neighbor_idx int32   [ne]
//   d_in[3] segment_ids  int32   [ne]   (sorted)
//   d_in[4] horizon      int32   [1]
// Output: float32 [n]
// ---------------------------------------------------------------------------

#define MAX_N   1048576   // supports n up to 1M (actual n = 200,000)
#define HMAX    16        // upper bound on horizon (actual = 10)

__device__ int   g_row_ptr[MAX_N + 1];
__device__ float g_gamma[2][MAX_N];

// row_ptr[j] = lower_bound(segment_ids, j); segment_ids is sorted, so each
// row's edge range is [row_ptr[j], row_ptr[j+1]). Empty rows handled naturally.
__global__ void build_row_ptr_kernel(const int* __restrict__ seg, int n_edges, int n) {
    int j = blockIdx.x * blockDim.x + threadIdx.x;
    if (j > n) return;
    int lo = 0, hi = n_edges;
    while (lo < hi) {
        int mid = (lo + hi) >> 1;
        if (__ldg(&seg[mid]) < j) lo = mid + 1;
        else                      hi = mid;
    }
    g_row_ptr[j] = lo;
}

__global__ void init_gamma_kernel(const float* __restrict__ g0, int n) {
    int i = blockIdx.x * blockDim.x + threadIdx.x;
    if (i < n) g_gamma[0][i] = g0[i];
}

// One warp per row. Steps with t >= *horizon are identity copies so the
// ping-pong parity stays deterministic without host-side readback.
__global__ void __launch_bounds__(256, 8)
step_kernel(const float* __restrict__ bl, const int* __restrict__ nbr,
            int n, int t, int parity, const int* __restrict__ hor) {
    int row  = (blockIdx.x * blockDim.x + threadIdx.x) >> 5;
    if (row >= n) return;
    int lane = threadIdx.x & 31;

    const float* __restrict__ gin  = g_gamma[parity];
    float*       __restrict__ gout = g_gamma[parity ^ 1];

    if (t >= __ldg(hor)) {              // identity pass-through step
        if (lane == 0) gout[row] = gin[row];
        return;
    }

    int beg = g_row_ptr[row];
    int end = g_row_ptr[row + 1];

    float s = 0.0f;
    for (int e = beg + lane; e < end; e += 32) {
        float b  = __ldg(&bl[e]);
        int   ix = __ldg(&nbr[e]);
        s = fmaf(b, 1.0f - __ldg(&gin[ix]), s);
    }
    #pragma unroll
    for (int o = 16; o; o >>= 1)
        s += __shfl_xor_sync(0xffffffffu, s, o);

    if (lane == 0) {
        float g = 1.0f - s;           // s >= 0 so g <= 1 already
        gout[row] = fminf(fmaxf(g, 0.0f), 1.0f);
    }
}

__global__ void writeout_kernel(float* __restrict__ out, int n) {
    int i = blockIdx.x * blockDim.x + threadIdx.x;
    if (i < n) out[i] = g_gamma[0][i];   // HMAX even -> result lands in buffer 0
}

extern "C" void kernel_launch(void* const* d_in, const int* in_sizes, int n_in,
                              void* d_out, int out_size) {
    const float* gamma0 = (const float*)d_in[0];
    const float* bl     = (const float*)d_in[1];
    const int*   nbr    = (const int*)d_in[2];
    const int*   seg    = (const int*)d_in[3];
    const int*   hor    = (const int*)d_in[4];

    int n  = in_sizes[0];
    int ne = in_sizes[1];

    build_row_ptr_kernel<<<(n + 1 + 255) / 256, 256>>>(seg, ne, n);
    init_gamma_kernel<<<(n + 255) / 256, 256>>>(gamma0, n);

    int rows_per_block = 256 / 32;
    int step_grid = (n + rows_per_block - 1) / rows_per_block;
    for (int t = 0; t < HMAX; t++) {
        step_kernel<<<step_grid, 256>>>(bl, nbr, n, t, t & 1, hor);
    }

    writeout_kernel<<<(n + 255) / 256, 256>>>((float*)d_out, n);
}